// round 1
// baseline (speedup 1.0000x reference)
#include <cuda_runtime.h>

// Problem constants
#define B_TOT   1024
#define T_SEQ   128
#define NB_     13
#define H_      128
#define G4_     512
#define T_IN_   64
#define BQ      8      // batch rows per block
#define NBLOCKS 128
#define NTHREADS 256
#define SW_COLS 384    // gate rows resident in smem (j < 384); j in [384,512) streamed from L2

// Shared memory layout (in floats)
#define SW_OFF   0                    // [128][384]  W_hh^T slice       49152
#define SH_OFF   49152                // [128][8]    h  [k][b]           1024
#define SF_OFF   50176                // [8][128]    f  [b][d]           1024
#define SO_OFF   51200                // [8][128]    o  [b][d]           1024
#define SWO_OFF  52224                // [13][132]   W_out padded        1716
#define SX_OFF   53940                // [13][8]     x_t [n][b] (pad)     112
#define SMEM_FLOATS 54052
#define SMEM_BYTES  (SMEM_FLOATS * 4)

// Device-global scratch (no runtime allocation allowed)
__device__ float g_WT[128 * 512];   // W_hh transposed: g_WT[k*512 + j] = W_hh[j][k]
__device__ float g_bias[512];       // b_ih + b_hh

// ---------- helpers ----------
__device__ __forceinline__ unsigned long long pk2(float v) {
    unsigned long long r;
    unsigned int u = __float_as_uint(v);
    asm("mov.b64 %0, {%1, %1};" : "=l"(r) : "r"(u));
    return r;
}
__device__ __forceinline__ void fma2(unsigned long long& a, unsigned long long b, unsigned long long c) {
    // packed 2x fp32 fma: a = b*c + a  (per 32-bit lane)
    asm("fma.rn.f32x2 %0, %1, %2, %0;" : "+l"(a) : "l"(b), "l"(c));
}
__device__ __forceinline__ float lo2(unsigned long long a) {
    return __uint_as_float((unsigned int)(a & 0xffffffffull));
}
__device__ __forceinline__ float hi2(unsigned long long a) {
    return __uint_as_float((unsigned int)(a >> 32));
}
__device__ __forceinline__ float sigm(float v) {
    return __fdividef(1.0f, 1.0f + __expf(-v));
}
__device__ __forceinline__ float tanh_(float v) {
    return __fdividef(2.0f, 1.0f + __expf(-2.0f * v)) - 1.0f;
}

// One 8-k chunk of the recurrent GEMM, with double-buffered L2 stream of the
// o-gate weight rows for threads t>=128 (j2 >= 384).
__device__ __forceinline__ void gate_chunk(
    int KC, bool hi_thread, bool do_pref,
    const float* __restrict__ sW, const unsigned long long* __restrict__ sH64,
    const float* __restrict__ gw, int j1, int j2,
    float (&wb)[8], float (&wbn)[8],
    unsigned long long (&a1)[4], unsigned long long (&a2)[4])
{
    if (hi_thread && do_pref) {
        #pragma unroll
        for (int u = 0; u < 8; u++) wbn[u] = __ldg(gw + ((KC + 1) * 8 + u) * 512);
    }
    #pragma unroll
    for (int u = 0; u < 8; u++) {
        int k = KC * 8 + u;
        float w1 = sW[k * SW_COLS + j1];
        float w2 = hi_thread ? wb[u] : sW[k * SW_COLS + j2];
        unsigned long long w1p = pk2(w1), w2p = pk2(w2);
        #pragma unroll
        for (int bp = 0; bp < 4; bp++) {
            unsigned long long hp = sH64[k * 4 + bp];   // broadcast LDS.64: h[k][2bp..2bp+1]
            fma2(a1[bp], hp, w1p);
            fma2(a2[bp], hp, w2p);
        }
    }
}

// ---------- prep: transpose W_hh, fuse biases ----------
__global__ void prep_kernel(const float* __restrict__ W_hh,
                            const float* __restrict__ b_ih,
                            const float* __restrict__ b_hh)
{
    int idx = blockIdx.x * blockDim.x + threadIdx.x;
    if (idx < 512 * 128) {
        int j = idx >> 7, k = idx & 127;
        g_WT[k * 512 + j] = W_hh[j * 128 + k];
    }
    if (idx < 512) g_bias[idx] = b_ih[idx] + b_hh[idx];
}

// ---------- main persistent LSTM kernel ----------
__global__ void __launch_bounds__(NTHREADS, 1)
lstm_kernel(const float* __restrict__ x, const float* __restrict__ W_ih,
            const float* __restrict__ W_out, const float* __restrict__ b_out,
            float* __restrict__ out)
{
    extern __shared__ float sm[];
    float* sW  = sm + SW_OFF;
    float* sH  = sm + SH_OFF;
    float* sF  = sm + SF_OFF;
    float* sO  = sm + SO_OFF;
    float* sWo = sm + SWO_OFF;
    float* sX  = sm + SX_OFF;

    const int t  = threadIdx.x;
    const int b0 = blockIdx.x * BQ;

    // Load W_hh^T slice (j<384) into smem
    for (int i = t; i < 128 * SW_COLS; i += NTHREADS) {
        int k = i / SW_COLS, j = i - k * SW_COLS;
        sW[i] = g_WT[k * 512 + j];
    }
    // W_out with padded stride 132 (bank-conflict relief)
    for (int i = t; i < NB_ * H_; i += NTHREADS) {
        int n = i >> 7, d = i & 127;
        sWo[n * 132 + d] = W_out[i];
    }
    // h = 0
    for (int i = t; i < H_ * BQ; i += NTHREADS) sH[i] = 0.0f;

    const int j1 = t, j2 = t + 256;
    const bool hi_thread = (t >= 128);
    const float* gw = g_WT + j2;        // streamed column for j2 >= 384

    float wih1[NB_], wih2[NB_];
    #pragma unroll
    for (int n = 0; n < NB_; n++) {
        wih1[n] = W_ih[j1 * NB_ + n];
        wih2[n] = W_ih[j2 * NB_ + n];
    }
    const float bs1 = g_bias[j1], bs2 = g_bias[j2];

    float c8[BQ];
    #pragma unroll
    for (int b = 0; b < BQ; b++) c8[b] = 0.0f;

    // readout mapping (104 threads: b = t/13, n = t%13)
    const int yb = t / NB_;
    const int yn = t - yb * NB_;
    const bool yth = (t < BQ * NB_);
    const float bo = yth ? __ldg(b_out + yn) : 0.0f;

    float xreg = 0.0f;
    if (yth) xreg = x[(b0 + yb) * (T_SEQ * NB_) + yn];   // x[:,0]

    __syncthreads();

    for (int s = 0; s < T_SEQ - 1; s++) {
        // input for this step: teacher x[:,s] for s<=64, else previous y (already in sX)
        if (s <= T_IN_ && yth) {
            sX[yn * 8 + yb] = xreg;
            if (s == 0) out[(b0 + yb) * (T_SEQ * NB_) + yn] = xreg;  // out[:,0] = x[:,0]
        }
        __syncthreads();
        if (s + 1 <= T_IN_ && yth)   // prefetch next teacher input (hidden under compute)
            xreg = x[(b0 + yb) * (T_SEQ * NB_) + (s + 1) * NB_ + yn];

        // ---- gates: a = bias + x@Wih^T + h@Whh^T (packed f32x2 over batch pairs) ----
        unsigned long long a1[4], a2[4];
        #pragma unroll
        for (int bp = 0; bp < 4; bp++) { a1[bp] = pk2(bs1); a2[bp] = pk2(bs2); }

        const unsigned long long* sX64 = (const unsigned long long*)sX;
        #pragma unroll
        for (int n = 0; n < NB_; n++) {
            unsigned long long w1p = pk2(wih1[n]), w2p = pk2(wih2[n]);
            #pragma unroll
            for (int bp = 0; bp < 4; bp++) {
                unsigned long long xp = sX64[n * 4 + bp];
                fma2(a1[bp], xp, w1p);
                fma2(a2[bp], xp, w2p);
            }
        }

        const unsigned long long* sH64 = (const unsigned long long*)(sm + SH_OFF);
        float wbuf0[8], wbuf1[8];
        if (hi_thread) {
            #pragma unroll
            for (int u = 0; u < 8; u++) wbuf0[u] = __ldg(gw + u * 512);
        }
        for (int kc2 = 0; kc2 < 8; kc2++) {
            gate_chunk(2 * kc2,     hi_thread, true,      sW, sH64, gw, j1, j2, wbuf0, wbuf1, a1, a2);
            gate_chunk(2 * kc2 + 1, hi_thread, kc2 < 7,   sW, sH64, gw, j1, j2, wbuf1, wbuf0, a1, a2);
        }

        // ---- activations + state update ----
        if (hi_thread) {
            // t in [128,256): owns f (j1) and o (j2) for dim d
            int d = t - 128;
            #pragma unroll
            for (int bp = 0; bp < 4; bp++) {
                sF[(2 * bp)     * 128 + d] = sigm(lo2(a1[bp]));
                sF[(2 * bp + 1) * 128 + d] = sigm(hi2(a1[bp]));
                sO[(2 * bp)     * 128 + d] = sigm(lo2(a2[bp]));
                sO[(2 * bp + 1) * 128 + d] = sigm(hi2(a2[bp]));
            }
        }
        __syncthreads();
        if (!hi_thread) {
            // t in [0,128): owns i (j1) and g (j2) for dim d; c lives in registers
            int d = t;
            float h8[BQ];
            #pragma unroll
            for (int bp = 0; bp < 4; bp++) {
                float iv0 = sigm(lo2(a1[bp])), iv1 = sigm(hi2(a1[bp]));
                float gv0 = tanh_(lo2(a2[bp])), gv1 = tanh_(hi2(a2[bp]));
                int b = 2 * bp;
                float c0 = fmaf(sF[b * 128 + d],       c8[b],     iv0 * gv0);
                float c1 = fmaf(sF[(b + 1) * 128 + d], c8[b + 1], iv1 * gv1);
                c8[b] = c0; c8[b + 1] = c1;
                h8[b]     = sO[b * 128 + d]       * tanh_(c0);
                h8[b + 1] = sO[(b + 1) * 128 + d] * tanh_(c1);
            }
            float4* sH4 = (float4*)(sm + SH_OFF);
            sH4[d * 2]     = make_float4(h8[0], h8[1], h8[2], h8[3]);
            sH4[d * 2 + 1] = make_float4(h8[4], h8[5], h8[6], h8[7]);
        }
        __syncthreads();

        // ---- readout y = h @ W_out^T + b_out ----
        if (yth) {
            float acc0 = bo, acc1v = 0.0f;
            #pragma unroll 4
            for (int d = 0; d < H_; d += 2) {
                acc0  = fmaf(sH[d * 8 + yb],       sWo[yn * 132 + d],     acc0);
                acc1v = fmaf(sH[(d + 1) * 8 + yb], sWo[yn * 132 + d + 1], acc1v);
            }
            float yv = acc0 + acc1v;
            out[(b0 + yb) * (T_SEQ * NB_) + (s + 1) * NB_ + yn] = yv;
            if (s >= T_IN_) sX[yn * 8 + yb] = yv;   // feedback for autoregressive phase
        }
        __syncthreads();
    }
}

extern "C" void kernel_launch(void* const* d_in, const int* in_sizes, int n_in,
                              void* d_out, int out_size)
{
    const float* x     = (const float*)d_in[0];
    const float* W_ih  = (const float*)d_in[1];
    const float* W_hh  = (const float*)d_in[2];
    const float* b_ih  = (const float*)d_in[3];
    const float* b_hh  = (const float*)d_in[4];
    const float* W_out = (const float*)d_in[5];
    const float* b_out = (const float*)d_in[6];
    float* out = (float*)d_out;

    cudaFuncSetAttribute(lstm_kernel, cudaFuncAttributeMaxDynamicSharedMemorySize, SMEM_BYTES);

    prep_kernel<<<256, 256>>>(W_hh, b_ih, b_hh);
    lstm_kernel<<<NBLOCKS, NTHREADS, SMEM_BYTES>>>(x, W_ih, W_out, b_out, out);
}